// round 13
// baseline (speedup 1.0000x reference)
#include <cuda_runtime.h>
#include <cuda_bf16.h>
#include <cstdint>

#define BB 8
#define CC 256
#define NNS 16384
#define BN_EPS 1e-5f
#define SPLITS 16

// ---------------- scratch (static device globals; no allocation allowed) ----------------
__device__ __align__(16) float g_k[(size_t)BB * CC * NNS];              // fp32 K = Wk @ X
__device__ __align__(16) float g_m[BB * CC];                            // per-row max
__device__ __align__(16) float g_s[BB * CC];                            // per-row 1/sum(exp)
__device__ __align__(16) float g_Spp[(size_t)SPLITS * BB * CC * CC];    // split-K partials
__device__ __align__(16) float g_Sp[BB * CC * CC];                      // S' reduced
__device__ __align__(16) float g_A0[CC * CC];                           // Wproj @ Wv
__device__ __align__(16) float g_U[BB * CC * CC];                       // weighted S'^T @ Wq
__device__ __align__(16) float g_P2[BB * CC * CC];                      // diag(inv) * A0 @ U (fp32)
__device__ __align__(16) __nv_bfloat16 g_xt_h[(size_t)BB * NNS * CC];   // X^T hi [b][n][c]
__device__ __align__(16) __nv_bfloat16 g_xt_l[(size_t)BB * NNS * CC];   // X^T lo
__device__ __align__(16) __nv_bfloat16 g_xn_h[(size_t)BB * CC * NNS];   // X   hi [b][c][n]
__device__ __align__(16) __nv_bfloat16 g_xn_l[(size_t)BB * CC * NNS];   // X   lo
__device__ __align__(16) __nv_bfloat16 g_e_h[(size_t)BB * CC * NNS];    // exp(K-m) hi [b][o][n]
__device__ __align__(16) __nv_bfloat16 g_e_l[(size_t)BB * CC * NNS];    // exp(K-m) lo

// ================= helpers (base-sm_103-safe PTX only) =================
__device__ __forceinline__ uint32_t smem_to_u32(const void* p) {
    uint32_t a;
    asm("{ .reg .u64 t; cvta.to.shared.u64 t, %1; cvt.u32.u64 %0, t; }" : "=r"(a) : "l"(p));
    return a;
}
__device__ __forceinline__ void ldsm4(uint32_t* r, uint32_t addr) {
    asm volatile("ldmatrix.sync.aligned.m8n8.x4.shared.b16 {%0,%1,%2,%3}, [%4];"
                 : "=r"(r[0]), "=r"(r[1]), "=r"(r[2]), "=r"(r[3]) : "r"(addr));
}
__device__ __forceinline__ void mma_bf16(float* c, const uint32_t* a, const uint32_t* b) {
    asm volatile("mma.sync.aligned.m16n8k16.row.col.f32.bf16.bf16.f32 "
                 "{%0,%1,%2,%3}, {%4,%5,%6,%7}, {%8,%9}, {%0,%1,%2,%3};"
                 : "+f"(c[0]), "+f"(c[1]), "+f"(c[2]), "+f"(c[3])
                 : "r"(a[0]), "r"(a[1]), "r"(a[2]), "r"(a[3]), "r"(b[0]), "r"(b[1]));
}
__device__ __forceinline__ void cp_async16(uint32_t dst, const void* src) {
    asm volatile("cp.async.cg.shared.global [%0], [%1], 16;" :: "r"(dst), "l"(src));
}
#define CP_COMMIT() asm volatile("cp.async.commit_group;" ::: "memory")
#define CP_WAIT0()  asm volatile("cp.async.wait_group 0;" ::: "memory")

__device__ __forceinline__ uint32_t pack2(float a, float b) {
    union { __nv_bfloat162 v; uint32_t u; } cv;
    cv.v = __floats2bfloat162_rn(a, b);
    return cv.u;
}
__device__ __forceinline__ float hi_of(float a) {
    return __bfloat162float(__float2bfloat16(a));
}

// ---------------- SMEM layouts: padded rows of 40 b16 (80 B) -> conflict-free ldmatrix ----------------
#define RSB 80
// ctx kernel (unchanged): A 128 rows, B 128 rows
#define OFF_AH 0
#define OFF_AL 10240
#define OFF_BH 20480
#define OFF_BL 30720
#define STAGE  40960
#define SMEM_CTX (2 * STAGE)            // 81920
// big kernel (merged M=256): A 256 rows, B 128 rows
#define BOFF_AH 0
#define BOFF_AL 20480
#define BOFF_BH 40960
#define BOFF_BL 51200
#define BSTAGE  61440
#define SMEM_BIG (2 * BSTAGE)           // 122880

// ---------------- X transpose + bf16 hi/lo split (both layouts) ----------------
__global__ void __launch_bounds__(256)
transpose_split(const float* __restrict__ x)
{
    __shared__ float sm[32][33];
    const int b = blockIdx.z, c0 = blockIdx.y * 32, n0 = blockIdx.x * 32;
    const int tx = threadIdx.x, ty = threadIdx.y;   // 32 x 8
    const float* xs = x + ((size_t)b * CC + c0) * NNS + n0;
    float v[4];
#pragma unroll
    for (int i = 0; i < 4; ++i) {
        v[i] = xs[(size_t)(ty + i * 8) * NNS + tx];
        sm[ty + i * 8][tx] = v[i];
    }
    const size_t nbase = ((size_t)b * CC + c0) * NNS + n0;
#pragma unroll
    for (int i = 0; i < 4; ++i) {
        int c = ty + i * 8;
        __nv_bfloat16 h = __float2bfloat16(v[i]);
        g_xn_h[nbase + (size_t)c * NNS + tx] = h;
        g_xn_l[nbase + (size_t)c * NNS + tx] = __float2bfloat16(v[i] - __bfloat162float(h));
    }
    __syncthreads();
    const size_t obase = ((size_t)b * NNS + n0) * CC + c0;
#pragma unroll
    for (int i = 0; i < 4; ++i) {
        int n = ty + i * 8;
        float f = sm[tx][n];
        __nv_bfloat16 h = __float2bfloat16(f);
        g_xt_h[obase + (size_t)n * CC + tx] = h;
        g_xt_l[obase + (size_t)n * CC + tx] = __float2bfloat16(f - __bfloat162float(h));
    }
}

// ---------------- big HMMA GEMM, merged M=256: D[b](256 x 128-tile) = A(256x256 fp32) @ Xt[b] ----------------
// MODE 0: A = Ap_ (Wk), D -> g_k.   MODE 1: A = g_P2[b], D -> outp with BN bias + ReLU.
// Warp layout: 2m x 4n; warp tile 128m x 32n (f in 0..7, proven p in 0..1 B-mapping).
template <int MODE>
__global__ void __launch_bounds__(256)
mma_big(const float* __restrict__ Ap_, float* __restrict__ outp,
        const float* __restrict__ gamma, const float* __restrict__ beta,
        const float* __restrict__ rmean, const float* __restrict__ rvar)
{
    extern __shared__ __align__(16) char smem[];
    const int tid = threadIdx.x, lid = tid & 31, wid = tid >> 5;
    const int wm = wid & 1, wn = wid >> 1;
    const int b = blockIdx.z, n0 = blockIdx.x * 128;
    const float* A = (MODE == 0) ? Ap_ : (g_P2 + (size_t)b * CC * CC);   // full 256 x 256
    const __nv_bfloat16* bhg = g_xt_h + ((size_t)b * NNS + n0) * CC;
    const __nv_bfloat16* blg = g_xt_l + ((size_t)b * NNS + n0) * CC;
    const uint32_t sb = smem_to_u32(smem);

    float acc[8][4][4];
#pragma unroll
    for (int f = 0; f < 8; ++f)
#pragma unroll
        for (int j = 0; j < 4; ++j)
#pragma unroll
            for (int e = 0; e < 4; ++e) acc[f][j][e] = 0.f;

    float4 areg[8];                      // register staging for next A slice (256x32 fp32)
    auto ldgA = [&](int ks) {
#pragma unroll
        for (int i = 0; i < 8; ++i) {
            int idx = tid + i * 256;             // 0..2047 float4s
            int r = idx >> 3, q = idx & 7;       // r 0..255, q 0..7
            areg[i] = *reinterpret_cast<const float4*>(A + ks * 32 + (size_t)r * CC + q * 4);
        }
    };
    auto stsA = [&](int st) {            // convert regs -> hi/lo bf16, store (proven math)
        char* bp = smem + st * BSTAGE;
#pragma unroll
        for (int i = 0; i < 8; ++i) {
            int idx = tid + i * 256;
            int r = idx >> 3, q = idx & 7;
            float4 v = areg[i];
            uint32_t h01 = pack2(v.x, v.y), h23 = pack2(v.z, v.w);
            uint32_t l01 = pack2(v.x - hi_of(v.x), v.y - hi_of(v.y));
            uint32_t l23 = pack2(v.z - hi_of(v.z), v.w - hi_of(v.w));
            *reinterpret_cast<uint2*>(bp + BOFF_AH + r * RSB + q * 8) = make_uint2(h01, h23);
            *reinterpret_cast<uint2*>(bp + BOFF_AL + r * RSB + q * 8) = make_uint2(l01, l23);
        }
    };
    auto loadB = [&](int ks, int st) {   // B 128 n-rows x 32 c, direct bf16 copies via cp.async
        uint32_t dst = sb + st * BSTAGE;
#pragma unroll
        for (int i = 0; i < 2; ++i) {
            int idx = tid + i * 256;             // 0..511 16B chunks
            int r = idx >> 2, q = idx & 3;
            cp_async16(dst + BOFF_BH + r * RSB + q * 16, bhg + (size_t)r * CC + ks * 32 + q * 8);
            cp_async16(dst + BOFF_BL + r * RSB + q * 16, blg + (size_t)r * CC + ks * 32 + q * 8);
        }
    };
    auto compute = [&](int st) {
        const uint32_t s0 = sb + st * BSTAGE;
#pragma unroll
        for (int k16 = 0; k16 < 2; ++k16) {
            const int ko = k16 * 16;
            uint32_t bhf[2][4], blf[2][4];
            const uint32_t bcol = (uint32_t)(ko + (((lid >> 3) & 1) << 3)) << 1;
#pragma unroll
            for (int p = 0; p < 2; ++p) {
                uint32_t nr = (uint32_t)(wn * 32 + p * 16 + (lid & 7) + ((lid >> 4) << 3));
                ldsm4(bhf[p], s0 + BOFF_BH + nr * RSB + bcol);
                ldsm4(blf[p], s0 + BOFF_BL + nr * RSB + bcol);
            }
            const uint32_t acol = (uint32_t)(ko + ((lid >> 4) << 3)) << 1;
#pragma unroll
            for (int f = 0; f < 8; ++f) {
                uint32_t ah[4], al[4];
                uint32_t row = (uint32_t)(wm * 128 + f * 16 + (lid & 15));
                ldsm4(ah, s0 + BOFF_AH + row * RSB + acol);
                ldsm4(al, s0 + BOFF_AL + row * RSB + acol);
#pragma unroll
                for (int j = 0; j < 4; ++j) {
                    const int p = j >> 1, h = j & 1;
                    uint32_t bh2[2] = {bhf[p][h * 2], bhf[p][h * 2 + 1]};
                    uint32_t bl2[2] = {blf[p][h * 2], blf[p][h * 2 + 1]};
                    mma_bf16(acc[f][j], ah, bh2);
                    mma_bf16(acc[f][j], ah, bl2);
                    mma_bf16(acc[f][j], al, bh2);
                }
            }
        }
    };

    // prologue: stage 0 fully populated before loop
    loadB(0, 0); CP_COMMIT();
    ldgA(0);
    stsA(0);
    for (int s = 0; s < 8; ++s) {
        CP_WAIT0();
        __syncthreads();
        if (s < 7) {
            loadB(s + 1, (s + 1) & 1);
            CP_COMMIT();
            ldgA(s + 1);                    // LDG latency overlaps compute(s)
        }
        compute(s & 1);
        if (s < 7) stsA((s + 1) & 1);
    }

    // epilogue
    float* outb = (MODE == 0 ? g_k : outp) + (size_t)b * CC * NNS;
    const int colb = n0 + wn * 32 + 2 * (lid & 3);
#pragma unroll
    for (int f = 0; f < 8; ++f) {
        const int r0 = wm * 128 + f * 16 + (lid >> 2);
        float bias0 = 0.f, bias1 = 0.f;
        if (MODE == 1) {
            float i0 = gamma[r0] * rsqrtf(rvar[r0] + BN_EPS);
            float i1 = gamma[r0 + 8] * rsqrtf(rvar[r0 + 8] + BN_EPS);
            bias0 = beta[r0] - rmean[r0] * i0;
            bias1 = beta[r0 + 8] - rmean[r0 + 8] * i1;
        }
#pragma unroll
        for (int j = 0; j < 4; ++j) {
            const int cc0 = colb + j * 8;
            float2 v0 = make_float2(acc[f][j][0], acc[f][j][1]);
            float2 v1 = make_float2(acc[f][j][2], acc[f][j][3]);
            if (MODE == 1) {
                v0.x = fmaxf(v0.x + bias0, 0.f); v0.y = fmaxf(v0.y + bias0, 0.f);
                v1.x = fmaxf(v1.x + bias1, 0.f); v1.y = fmaxf(v1.y + bias1, 0.f);
            }
            *reinterpret_cast<float2*>(outb + (size_t)r0 * NNS + cc0)       = v0;
            *reinterpret_cast<float2*>(outb + (size_t)(r0 + 8) * NNS + cc0) = v1;
        }
    }
}

// ---------------- ctx HMMA GEMM (R12 VERBATIM): S'_partial = E @ Xn^T over 1024 n ----------------
__global__ void __launch_bounds__(256)
mma_ctx()
{
    extern __shared__ __align__(16) char smem[];
    const int tid = threadIdx.x, lid = tid & 31, wid = tid >> 5;
    const int wm = wid & 1, wn = wid >> 1;
    const int o0 = (blockIdx.x >> 1) * 128, c0 = (blockIdx.x & 1) * 128;
    const int split = blockIdx.y, b = blockIdx.z;
    const uint32_t sb = smem_to_u32(smem);

    const size_t ko0 = (size_t)split * 1024;
    const __nv_bfloat16* ehg = g_e_h + ((size_t)b * CC + o0) * NNS + ko0;
    const __nv_bfloat16* elg = g_e_l + ((size_t)b * CC + o0) * NNS + ko0;
    const __nv_bfloat16* xhg = g_xn_h + ((size_t)b * CC + c0) * NNS + ko0;
    const __nv_bfloat16* xlg = g_xn_l + ((size_t)b * CC + c0) * NNS + ko0;

    float acc[4][4][4];
#pragma unroll
    for (int f = 0; f < 4; ++f)
#pragma unroll
        for (int j = 0; j < 4; ++j)
#pragma unroll
            for (int e = 0; e < 4; ++e) acc[f][j][e] = 0.f;

    auto loadT = [&](int ks, int st) {
        uint32_t dst = sb + st * STAGE;
#pragma unroll
        for (int i = 0; i < 2; ++i) {
            int idx = tid + i * 256;             // 0..511 16B chunks
            int r = idx >> 2, q = idx & 3;
            size_t so = (size_t)r * NNS + (size_t)ks * 32 + q * 8;
            cp_async16(dst + OFF_AH + r * RSB + q * 16, ehg + so);
            cp_async16(dst + OFF_AL + r * RSB + q * 16, elg + so);
            cp_async16(dst + OFF_BH + r * RSB + q * 16, xhg + so);
            cp_async16(dst + OFF_BL + r * RSB + q * 16, xlg + so);
        }
    };
    auto compute = [&](int st) {
        const uint32_t s0 = sb + st * STAGE;
#pragma unroll
        for (int k16 = 0; k16 < 2; ++k16) {
            const int ko = k16 * 16;
            uint32_t ah[4][4], al[4][4], bhf[2][4], blf[2][4];
            const uint32_t acol = (uint32_t)(ko + ((lid >> 4) << 3)) << 1;
#pragma unroll
            for (int f = 0; f < 4; ++f) {
                uint32_t row = (uint32_t)(wm * 64 + f * 16 + (lid & 15));
                ldsm4(ah[f], s0 + OFF_AH + row * RSB + acol);
                ldsm4(al[f], s0 + OFF_AL + row * RSB + acol);
            }
            const uint32_t bcol = (uint32_t)(ko + (((lid >> 3) & 1) << 3)) << 1;
#pragma unroll
            for (int p = 0; p < 2; ++p) {
                uint32_t nr = (uint32_t)(wn * 32 + p * 16 + (lid & 7) + ((lid >> 4) << 3));
                ldsm4(bhf[p], s0 + OFF_BH + nr * RSB + bcol);
                ldsm4(blf[p], s0 + OFF_BL + nr * RSB + bcol);
            }
#pragma unroll
            for (int f = 0; f < 4; ++f)
#pragma unroll
                for (int j = 0; j < 4; ++j) {
                    const int p = j >> 1, h = j & 1;
                    uint32_t bh2[2] = {bhf[p][h * 2], bhf[p][h * 2 + 1]};
                    uint32_t bl2[2] = {blf[p][h * 2], blf[p][h * 2 + 1]};
                    mma_bf16(acc[f][j], ah[f], bh2);
                    mma_bf16(acc[f][j], ah[f], bl2);
                    mma_bf16(acc[f][j], al[f], bh2);
                }
        }
    };

    loadT(0, 0); CP_COMMIT();
    for (int s = 0; s < 32; ++s) {
        CP_WAIT0();
        __syncthreads();
        if (s < 31) { loadT(s + 1, (s + 1) & 1); CP_COMMIT(); }
        compute(s & 1);
    }

    float* dstb = g_Spp + ((size_t)split * BB + b) * CC * CC;
    const int colb = c0 + wn * 32 + 2 * (lid & 3);
#pragma unroll
    for (int f = 0; f < 4; ++f) {
        const int r0 = o0 + wm * 64 + f * 16 + (lid >> 2);
#pragma unroll
        for (int j = 0; j < 4; ++j) {
            const int cc0 = colb + j * 8;
            *reinterpret_cast<float2*>(dstb + (size_t)r0 * CC + cc0) =
                make_float2(acc[f][j][0], acc[f][j][1]);
            *reinterpret_cast<float2*>(dstb + (size_t)(r0 + 8) * CC + cc0) =
                make_float2(acc[f][j][2], acc[f][j][3]);
        }
    }
}

// ---------------- per-row max + 1/sum(exp) + E=exp(K-m) bf16 hi/lo writeback ----------------
__global__ void __launch_bounds__(256)
rowstats_econv()
{
    const size_t row = blockIdx.x;  // 0..2047 == b*256 + o
    const float4* kr = reinterpret_cast<const float4*>(g_k) + row * (NNS / 4);
    const int t = threadIdx.x;

    float4 v[16];
    float mx = -3.402823466e38f;
#pragma unroll
    for (int i = 0; i < 16; ++i) {
        v[i] = kr[t + (i << 8)];
        mx = fmaxf(mx, fmaxf(fmaxf(v[i].x, v[i].y), fmaxf(v[i].z, v[i].w)));
    }
    __shared__ float red[8];
    __shared__ float bmax;
#pragma unroll
    for (int o = 16; o; o >>= 1) mx = fmaxf(mx, __shfl_xor_sync(0xffffffffu, mx, o));
    if ((t & 31) == 0) red[t >> 5] = mx;
    __syncthreads();
    if (t < 32) {
        float x2 = (t < 8) ? red[t] : -3.402823466e38f;
#pragma unroll
        for (int o = 4; o; o >>= 1) x2 = fmaxf(x2, __shfl_xor_sync(0xffffffffu, x2, o));
        if (t == 0) bmax = x2;
    }
    __syncthreads();
    const float m = bmax;

    uint2* eh = reinterpret_cast<uint2*>(g_e_h + row * NNS);
    uint2* el = reinterpret_cast<uint2*>(g_e_l + row * NNS);
    float s = 0.f;
#pragma unroll
    for (int i = 0; i < 16; ++i) {
        float ex = __expf(v[i].x - m), ey = __expf(v[i].y - m);
        float ez = __expf(v[i].z - m), ew = __expf(v[i].w - m);
        s += ex + ey + ez + ew;
        const int q = t + (i << 8);
        eh[q] = make_uint2(pack2(ex, ey), pack2(ez, ew));
        el[q] = make_uint2(pack2(ex - hi_of(ex), ey - hi_of(ey)),
                           pack2(ez - hi_of(ez), ew - hi_of(ew)));
    }
#pragma unroll
    for (int o = 16; o; o >>= 1) s += __shfl_xor_sync(0xffffffffu, s, o);
    if ((t & 31) == 0) red[t >> 5] = s;
    __syncthreads();
    if (t < 32) {
        float x2 = (t < 8) ? red[t] : 0.f;
#pragma unroll
        for (int o = 4; o; o >>= 1) x2 += __shfl_xor_sync(0xffffffffu, x2, o);
        if (t == 0) { g_m[row] = m; g_s[row] = 1.0f / x2; }
    }
}

// ---------------- reduce the 16 split partials into g_Sp ----------------
__global__ void __launch_bounds__(256)
reduce_sp()
{
    const int idx = blockIdx.x * 256 + threadIdx.x;
    const float4* src = reinterpret_cast<const float4*>(g_Spp);
    float4 a = make_float4(0.f, 0.f, 0.f, 0.f);
#pragma unroll
    for (int s = 0; s < SPLITS; ++s) {
        float4 v = src[(long)s * (BB * CC * CC / 4) + idx];
        a.x += v.x; a.y += v.y; a.z += v.z; a.w += v.w;
    }
    reinterpret_cast<float4*>(g_Sp)[idx] = a;
}

// ---------------- small 256^3 GEMMs (R8 VERBATIM, fp32 P2 output) ----------------
template <int MODE>
__global__ void __launch_bounds__(256)
sgemm_small(const float* __restrict__ in0, const float* __restrict__ in1,
            const float* __restrict__ gamma, const float* __restrict__ rvar)
{
    const int LD = CC;
    const int b = blockIdx.z;
    const float* A = (MODE == 0) ? in0 : (MODE == 1) ? (g_Sp + (long)b * CC * CC) : g_A0;
    const float* Bm = (MODE == 0) ? in1 : (MODE == 1) ? in0 : (g_U + (long)b * CC * CC);
    float* Cm = (MODE == 0) ? g_A0 : (MODE == 1) ? (g_U + (long)b * CC * CC)
                                                  : (g_P2 + (long)b * CC * CC);
    const float* ks = (MODE == 1) ? (g_s + (long)b * CC) : nullptr;
    const int m0 = blockIdx.y * 64, n0 = blockIdx.x * 64;

    __shared__ float As[16][65];
    __shared__ float Bs[16][65];

    const int tid = threadIdx.x;
    const int tx = tid & 15, ty = tid >> 4;
    float acc[4][4] = {};

    for (int k0 = 0; k0 < CC; k0 += 16) {
#pragma unroll
        for (int p = 0; p < 4; ++p) {
            int idx = tid + p * 256;
            if (MODE == 1) {
                int kk = idx >> 6, mm = idx & 63;
                As[kk][mm] = A[(long)(k0 + kk) * LD + m0 + mm] * ks[k0 + kk];
            } else {
                int mm = idx >> 4, kk = idx & 15;
                As[kk][mm] = A[(long)(m0 + mm) * LD + k0 + kk];
            }
            int kk2 = idx >> 6, nn2 = idx & 63;
            Bs[kk2][nn2] = Bm[(long)(k0 + kk2) * LD + n0 + nn2];
        }
        __syncthreads();
#pragma unroll
        for (int kk = 0; kk < 16; ++kk) {
            float a[4], bb[4];
#pragma unroll
            for (int i = 0; i < 4; ++i) { a[i] = As[kk][ty * 4 + i]; bb[i] = Bs[kk][tx * 4 + i]; }
#pragma unroll
            for (int i = 0; i < 4; ++i)
#pragma unroll
                for (int j = 0; j < 4; ++j) acc[i][j] += a[i] * bb[j];
        }
        __syncthreads();
    }

#pragma unroll
    for (int i = 0; i < 4; ++i) {
        int mg = m0 + ty * 4 + i;
        float sc = (MODE == 2) ? gamma[mg] * rsqrtf(rvar[mg] + BN_EPS) : 1.f;
#pragma unroll
        for (int j = 0; j < 4; ++j)
            Cm[(long)mg * LD + n0 + tx * 4 + j] = acc[i][j] * sc;
    }
}

// ---------------- launch ----------------
extern "C" void kernel_launch(void* const* d_in, const int* in_sizes, int n_in,
                              void* d_out, int out_size)
{
    const float* x      = (const float*)d_in[0];
    const float* w_qkv  = (const float*)d_in[1];
    const float* w_proj = (const float*)d_in[2];
    const float* gamma  = (const float*)d_in[3];
    const float* beta   = (const float*)d_in[4];
    const float* rmean  = (const float*)d_in[5];
    const float* rvar   = (const float*)d_in[6];
    float* out = (float*)d_out;

    cudaFuncSetAttribute((const void*)mma_big<0>, cudaFuncAttributeMaxDynamicSharedMemorySize, SMEM_BIG);
    cudaFuncSetAttribute((const void*)mma_big<1>, cudaFuncAttributeMaxDynamicSharedMemorySize, SMEM_BIG);
    cudaFuncSetAttribute((const void*)mma_ctx,    cudaFuncAttributeMaxDynamicSharedMemorySize, SMEM_CTX);

    // 0) X -> xt (transposed) and xn (straight) bf16 hi/lo
    transpose_split<<<dim3(NNS / 32, CC / 32, BB), dim3(32, 8)>>>(x);

    // 1) g_k = Wk @ X   (Wk = w_qkv rows [256,512); merged M=256 per CTA)
    mma_big<0><<<dim3(NNS / 128, 1, BB), 256, SMEM_BIG>>>(w_qkv + CC * CC, nullptr,
                                                          nullptr, nullptr, nullptr, nullptr);

    // 2) softmax stats + E = exp(K-m) bf16 hi/lo
    rowstats_econv<<<BB * CC, 256>>>();

    // 3) split-K partials: E @ X^T -> g_Spp
    mma_ctx<<<dim3(4, SPLITS, BB), 256, SMEM_CTX>>>();

    // 3b) reduce partials -> g_Sp
    reduce_sp<<<512, 256>>>();

    // 4) g_A0 = Wproj @ Wv
    sgemm_small<0><<<dim3(4, 4, 1), 256>>>(w_proj, w_qkv + 2 * CC * CC, nullptr, nullptr);

    // 5) g_U[b] = diag(1/s)-weighted S'^T @ Wq
    sgemm_small<1><<<dim3(4, 4, BB), 256>>>(w_qkv, nullptr, nullptr, nullptr);

    // 6) g_P2[b] (fp32) = diag(inv) * (A0 @ U[b])
    sgemm_small<2><<<dim3(4, 4, BB), 256>>>(nullptr, nullptr, gamma, rvar);

    // 7) out = relu(P2 @ X + (beta - mean*inv))
    mma_big<1><<<dim3(NNS / 128, 1, BB), 256, SMEM_BIG>>>(nullptr, out,
                                                          gamma, beta, rmean, rvar);
}

// round 16
// speedup vs baseline: 1.4673x; 1.4673x over previous
#include <cuda_runtime.h>
#include <cuda_bf16.h>
#include <cstdint>

#define BB 8
#define CC 256
#define NNS 16384
#define BN_EPS 1e-5f
#define SPLITS 16

// ---------------- scratch (static device globals; no allocation allowed) ----------------
__device__ __align__(16) float g_k[(size_t)BB * CC * NNS];              // fp32 K = Wk @ X
__device__ __align__(16) float g_m[BB * CC];                            // per-row max
__device__ __align__(16) float g_s[BB * CC];                            // per-row 1/sum(exp)
__device__ __align__(16) float g_Spp[(size_t)SPLITS * BB * CC * CC];    // split-K partials
__device__ __align__(16) float g_Sp[BB * CC * CC];                      // S' reduced
__device__ __align__(16) float g_A0[CC * CC];                           // Wproj @ Wv
__device__ __align__(16) float g_U[BB * CC * CC];                       // weighted S'^T @ Wq
__device__ __align__(16) float g_P2[BB * CC * CC];                      // diag(inv) * A0 @ U (fp32)
__device__ __align__(16) __nv_bfloat16 g_xt_h[(size_t)BB * NNS * CC];   // X^T hi [b][n][c]
__device__ __align__(16) __nv_bfloat16 g_xt_l[(size_t)BB * NNS * CC];   // X^T lo
__device__ __align__(16) __nv_bfloat16 g_xn_h[(size_t)BB * CC * NNS];   // X   hi [b][c][n]
__device__ __align__(16) __nv_bfloat16 g_xn_l[(size_t)BB * CC * NNS];   // X   lo
__device__ __align__(16) __nv_bfloat16 g_e_h[(size_t)BB * CC * NNS];    // exp(K-m) hi [b][o][n]
__device__ __align__(16) __nv_bfloat16 g_e_l[(size_t)BB * CC * NNS];    // exp(K-m) lo

// ================= helpers (base-sm_103-safe PTX only) =================
__device__ __forceinline__ uint32_t smem_to_u32(const void* p) {
    uint32_t a;
    asm("{ .reg .u64 t; cvta.to.shared.u64 t, %1; cvt.u32.u64 %0, t; }" : "=r"(a) : "l"(p));
    return a;
}
__device__ __forceinline__ void ldsm4(uint32_t* r, uint32_t addr) {
    asm volatile("ldmatrix.sync.aligned.m8n8.x4.shared.b16 {%0,%1,%2,%3}, [%4];"
                 : "=r"(r[0]), "=r"(r[1]), "=r"(r[2]), "=r"(r[3]) : "r"(addr));
}
__device__ __forceinline__ void mma_bf16(float* c, const uint32_t* a, const uint32_t* b) {
    asm volatile("mma.sync.aligned.m16n8k16.row.col.f32.bf16.bf16.f32 "
                 "{%0,%1,%2,%3}, {%4,%5,%6,%7}, {%8,%9}, {%0,%1,%2,%3};"
                 : "+f"(c[0]), "+f"(c[1]), "+f"(c[2]), "+f"(c[3])
                 : "r"(a[0]), "r"(a[1]), "r"(a[2]), "r"(a[3]), "r"(b[0]), "r"(b[1]));
}
__device__ __forceinline__ void cp_async16(uint32_t dst, const void* src) {
    asm volatile("cp.async.cg.shared.global [%0], [%1], 16;" :: "r"(dst), "l"(src));
}
#define CP_COMMIT() asm volatile("cp.async.commit_group;" ::: "memory")
#define CP_WAIT2()  asm volatile("cp.async.wait_group 2;" ::: "memory")

__device__ __forceinline__ uint32_t pack2(float a, float b) {
    union { __nv_bfloat162 v; uint32_t u; } cv;
    cv.v = __floats2bfloat162_rn(a, b);
    return cv.u;
}
__device__ __forceinline__ float hi_of(float a) {
    return __bfloat162float(__float2bfloat16(a));
}

// ---------------- SMEM layout: k16 stages, rows padded to 48 B ----------------
// 48 is a multiple of 16 -> every cp.async / ldmatrix / uint2 address is aligned.
// Bank check (ldmatrix, 8 rows x 16B): r*48 mod 128 = {0,48,96,16,64,112,32,80} distinct -> conflict-free.
#define RSB16 48
#define SOFF_AH 0
#define SOFF_AL 6144
#define SOFF_BH 12288
#define SOFF_BL 18432
#define STAGE16 24576
#define SMEM_MMA (4 * STAGE16)          // 98304, quad buffered (2 CTAs/SM)

// ---------------- X transpose + bf16 hi/lo split (both layouts) ----------------
__global__ void __launch_bounds__(256)
transpose_split(const float* __restrict__ x)
{
    __shared__ float sm[32][33];
    const int b = blockIdx.z, c0 = blockIdx.y * 32, n0 = blockIdx.x * 32;
    const int tx = threadIdx.x, ty = threadIdx.y;   // 32 x 8
    const float* xs = x + ((size_t)b * CC + c0) * NNS + n0;
    float v[4];
#pragma unroll
    for (int i = 0; i < 4; ++i) {
        v[i] = xs[(size_t)(ty + i * 8) * NNS + tx];
        sm[ty + i * 8][tx] = v[i];
    }
    const size_t nbase = ((size_t)b * CC + c0) * NNS + n0;
#pragma unroll
    for (int i = 0; i < 4; ++i) {
        int c = ty + i * 8;
        __nv_bfloat16 h = __float2bfloat16(v[i]);
        g_xn_h[nbase + (size_t)c * NNS + tx] = h;
        g_xn_l[nbase + (size_t)c * NNS + tx] = __float2bfloat16(v[i] - __bfloat162float(h));
    }
    __syncthreads();
    const size_t obase = ((size_t)b * NNS + n0) * CC + c0;
#pragma unroll
    for (int i = 0; i < 4; ++i) {
        int n = ty + i * 8;
        float f = sm[tx][n];
        __nv_bfloat16 h = __float2bfloat16(f);
        g_xt_h[obase + (size_t)n * CC + tx] = h;
        g_xt_l[obase + (size_t)n * CC + tx] = __float2bfloat16(f - __bfloat162float(h));
    }
}

// ---------------- big HMMA GEMM: D[b](128m x 128n tile) = A(fp32, reg-pipelined) @ Xt[b] ----------------
// MODE 0: A = Ap_ (Wk), D -> g_k.   MODE 1: A = g_P2[b], D -> outp with BN bias + ReLU.
// 4-stage k16 pipeline, loads 3 ahead. Warp tile 64m x 32n (acc = 64 regs, R12-proven mapping).
template <int MODE>
__global__ void __launch_bounds__(256)
mma_big(const float* __restrict__ Ap_, float* __restrict__ outp,
        const float* __restrict__ gamma, const float* __restrict__ beta,
        const float* __restrict__ rmean, const float* __restrict__ rvar)
{
    extern __shared__ __align__(16) char smem[];
    const int tid = threadIdx.x, lid = tid & 31, wid = tid >> 5;
    const int wm = wid & 1, wn = wid >> 1;
    const int b = blockIdx.z, m0 = blockIdx.y * 128, n0 = blockIdx.x * 128;
    const float* A = ((MODE == 0) ? Ap_ : (g_P2 + (size_t)b * CC * CC)) + (size_t)m0 * CC;
    const __nv_bfloat16* bhg = g_xt_h + ((size_t)b * NNS + n0) * CC;
    const __nv_bfloat16* blg = g_xt_l + ((size_t)b * NNS + n0) * CC;
    const uint32_t sb = smem_to_u32(smem);

    float acc[4][4][4];
#pragma unroll
    for (int f = 0; f < 4; ++f)
#pragma unroll
        for (int j = 0; j < 4; ++j)
#pragma unroll
            for (int e = 0; e < 4; ++e) acc[f][j][e] = 0.f;

    float4 areg[2];                      // register staging for next A k16 slice (128x16 fp32)
    auto ldgA = [&](int ks) {
#pragma unroll
        for (int i = 0; i < 2; ++i) {
            int idx = tid + i * 256;             // 0..511 float4s
            int r = idx >> 2, q = idx & 3;       // r 0..127, q 0..3
            areg[i] = *reinterpret_cast<const float4*>(A + ks * 16 + (size_t)r * CC + q * 4);
        }
    };
    auto stsA = [&](int st) {            // convert regs -> hi/lo bf16, store (proven math)
        char* bp = smem + st * STAGE16;
#pragma unroll
        for (int i = 0; i < 2; ++i) {
            int idx = tid + i * 256;
            int r = idx >> 2, q = idx & 3;
            float4 v = areg[i];
            uint32_t h01 = pack2(v.x, v.y), h23 = pack2(v.z, v.w);
            uint32_t l01 = pack2(v.x - hi_of(v.x), v.y - hi_of(v.y));
            uint32_t l23 = pack2(v.z - hi_of(v.z), v.w - hi_of(v.w));
            *reinterpret_cast<uint2*>(bp + SOFF_AH + r * RSB16 + q * 8) = make_uint2(h01, h23);
            *reinterpret_cast<uint2*>(bp + SOFF_AL + r * RSB16 + q * 8) = make_uint2(l01, l23);
        }
    };
    auto loadB = [&](int ks, int st) {   // B 128 n-rows x 16 c bf16 hi/lo, one 16B chunk each
        uint32_t dst = sb + st * STAGE16;
        int r = tid >> 1, q = tid & 1;           // 128 rows x 2 chunks
        cp_async16(dst + SOFF_BH + r * RSB16 + q * 16, bhg + (size_t)r * CC + ks * 16 + q * 8);
        cp_async16(dst + SOFF_BL + r * RSB16 + q * 16, blg + (size_t)r * CC + ks * 16 + q * 8);
    };
    auto compute = [&](int st) {         // one k16 block (R12 body minus ko term)
        const uint32_t s0 = sb + st * STAGE16;
        uint32_t ah[4][4], al[4][4], bhf[2][4], blf[2][4];
        const uint32_t acol = (uint32_t)((lid >> 4) << 3) << 1;
#pragma unroll
        for (int f = 0; f < 4; ++f) {
            uint32_t row = (uint32_t)(wm * 64 + f * 16 + (lid & 15));
            ldsm4(ah[f], s0 + SOFF_AH + row * RSB16 + acol);
            ldsm4(al[f], s0 + SOFF_AL + row * RSB16 + acol);
        }
        const uint32_t bcol = (uint32_t)(((lid >> 3) & 1) << 3) << 1;
#pragma unroll
        for (int p = 0; p < 2; ++p) {
            uint32_t nr = (uint32_t)(wn * 32 + p * 16 + (lid & 7) + ((lid >> 4) << 3));
            ldsm4(bhf[p], s0 + SOFF_BH + nr * RSB16 + bcol);
            ldsm4(blf[p], s0 + SOFF_BL + nr * RSB16 + bcol);
        }
#pragma unroll
        for (int f = 0; f < 4; ++f)
#pragma unroll
            for (int j = 0; j < 4; ++j) {
                const int p = j >> 1, h = j & 1;
                uint32_t bh2[2] = {bhf[p][h * 2], bhf[p][h * 2 + 1]};
                uint32_t bl2[2] = {blf[p][h * 2], blf[p][h * 2 + 1]};
                mma_bf16(acc[f][j], ah[f], bh2);
                mma_bf16(acc[f][j], ah[f], bl2);
                mma_bf16(acc[f][j], al[f], bh2);
            }
    };

    // prologue: stages 0,1,2
    loadB(0, 0); CP_COMMIT();
    loadB(1, 1); CP_COMMIT();
    loadB(2, 2); CP_COMMIT();
    ldgA(0); stsA(0);
    ldgA(1); stsA(1);
    ldgA(2); stsA(2);
    const int S = 16;                    // K=256 / 16
    for (int s = 0; s < S; ++s) {
        CP_WAIT2();                      // group s complete (s+1, s+2 may be in flight)
        __syncthreads();                 // all warps done compute(s-1) -> buf (s+3)&3 free
        const bool pf = (s + 3 < S);
        if (pf) { loadB(s + 3, (s + 3) & 3); ldgA(s + 3); }
        CP_COMMIT();                     // always commit (possibly empty) to keep group count aligned
        compute(s & 3);
        if (pf) stsA((s + 3) & 3);       // visible to others by next iteration's barrier
    }

    // epilogue (R12 verbatim)
    float* outb = (MODE == 0 ? g_k : outp) + (size_t)b * CC * NNS;
    const int colb = n0 + wn * 32 + 2 * (lid & 3);
#pragma unroll
    for (int f = 0; f < 4; ++f) {
        const int r0 = m0 + wm * 64 + f * 16 + (lid >> 2);
        float bias0 = 0.f, bias1 = 0.f;
        if (MODE == 1) {
            float i0 = gamma[r0] * rsqrtf(rvar[r0] + BN_EPS);
            float i1 = gamma[r0 + 8] * rsqrtf(rvar[r0 + 8] + BN_EPS);
            bias0 = beta[r0] - rmean[r0] * i0;
            bias1 = beta[r0 + 8] - rmean[r0 + 8] * i1;
        }
#pragma unroll
        for (int j = 0; j < 4; ++j) {
            const int cc0 = colb + j * 8;
            float2 v0 = make_float2(acc[f][j][0], acc[f][j][1]);
            float2 v1 = make_float2(acc[f][j][2], acc[f][j][3]);
            if (MODE == 1) {
                v0.x = fmaxf(v0.x + bias0, 0.f); v0.y = fmaxf(v0.y + bias0, 0.f);
                v1.x = fmaxf(v1.x + bias1, 0.f); v1.y = fmaxf(v1.y + bias1, 0.f);
            }
            *reinterpret_cast<float2*>(outb + (size_t)r0 * NNS + cc0)       = v0;
            *reinterpret_cast<float2*>(outb + (size_t)(r0 + 8) * NNS + cc0) = v1;
        }
    }
}

// ---------------- ctx HMMA GEMM: S'_partial = E(hi/lo) @ Xn(hi/lo)^T over 1024 n, 4-stage k16 ----------------
__global__ void __launch_bounds__(256)
mma_ctx()
{
    extern __shared__ __align__(16) char smem[];
    const int tid = threadIdx.x, lid = tid & 31, wid = tid >> 5;
    const int wm = wid & 1, wn = wid >> 1;
    const int o0 = (blockIdx.x >> 1) * 128, c0 = (blockIdx.x & 1) * 128;
    const int split = blockIdx.y, b = blockIdx.z;
    const uint32_t sb = smem_to_u32(smem);

    const size_t ko0 = (size_t)split * 1024;
    const __nv_bfloat16* ehg = g_e_h + ((size_t)b * CC + o0) * NNS + ko0;
    const __nv_bfloat16* elg = g_e_l + ((size_t)b * CC + o0) * NNS + ko0;
    const __nv_bfloat16* xhg = g_xn_h + ((size_t)b * CC + c0) * NNS + ko0;
    const __nv_bfloat16* xlg = g_xn_l + ((size_t)b * CC + c0) * NNS + ko0;

    float acc[4][4][4];
#pragma unroll
    for (int f = 0; f < 4; ++f)
#pragma unroll
        for (int j = 0; j < 4; ++j)
#pragma unroll
            for (int e = 0; e < 4; ++e) acc[f][j][e] = 0.f;

    auto loadT = [&](int ks, int st) {   // all four streams, one 16B chunk per thread each
        uint32_t dst = sb + st * STAGE16;
        int r = tid >> 1, q = tid & 1;           // 128 rows x 2 chunks
        size_t so = (size_t)r * NNS + (size_t)ks * 16 + q * 8;
        cp_async16(dst + SOFF_AH + r * RSB16 + q * 16, ehg + so);
        cp_async16(dst + SOFF_AL + r * RSB16 + q * 16, elg + so);
        cp_async16(dst + SOFF_BH + r * RSB16 + q * 16, xhg + so);
        cp_async16(dst + SOFF_BL + r * RSB16 + q * 16, xlg + so);
    };
    auto compute = [&](int st) {         // one k16 block
        const uint32_t s0 = sb + st * STAGE16;
        uint32_t ah[4][4], al[4][4], bhf[2][4], blf[2][4];
        const uint32_t acol = (uint32_t)((lid >> 4) << 3) << 1;
#pragma unroll
        for (int f = 0; f < 4; ++f) {
            uint32_t row = (uint32_t)(wm * 64 + f * 16 + (lid & 15));
            ldsm4(ah[f], s0 + SOFF_AH + row * RSB16 + acol);
            ldsm4(al[f], s0 + SOFF_AL + row * RSB16 + acol);
        }
        const uint32_t bcol = (uint32_t)(((lid >> 3) & 1) << 3) << 1;
#pragma unroll
        for (int p = 0; p < 2; ++p) {
            uint32_t nr = (uint32_t)(wn * 32 + p * 16 + (lid & 7) + ((lid >> 4) << 3));
            ldsm4(bhf[p], s0 + SOFF_BH + nr * RSB16 + bcol);
            ldsm4(blf[p], s0 + SOFF_BL + nr * RSB16 + bcol);
        }
#pragma unroll
        for (int f = 0; f < 4; ++f)
#pragma unroll
            for (int j = 0; j < 4; ++j) {
                const int p = j >> 1, h = j & 1;
                uint32_t bh2[2] = {bhf[p][h * 2], bhf[p][h * 2 + 1]};
                uint32_t bl2[2] = {blf[p][h * 2], blf[p][h * 2 + 1]};
                mma_bf16(acc[f][j], ah[f], bh2);
                mma_bf16(acc[f][j], ah[f], bl2);
                mma_bf16(acc[f][j], al[f], bh2);
            }
    };

    loadT(0, 0); CP_COMMIT();
    loadT(1, 1); CP_COMMIT();
    loadT(2, 2); CP_COMMIT();
    const int S = 64;                    // 1024 / 16
    for (int s = 0; s < S; ++s) {
        CP_WAIT2();
        __syncthreads();
        if (s + 3 < S) loadT(s + 3, (s + 3) & 3);
        CP_COMMIT();
        compute(s & 3);
    }

    // epilogue (R12 verbatim)
    float* dstb = g_Spp + ((size_t)split * BB + b) * CC * CC;
    const int colb = c0 + wn * 32 + 2 * (lid & 3);
#pragma unroll
    for (int f = 0; f < 4; ++f) {
        const int r0 = o0 + wm * 64 + f * 16 + (lid >> 2);
#pragma unroll
        for (int j = 0; j < 4; ++j) {
            const int cc0 = colb + j * 8;
            *reinterpret_cast<float2*>(dstb + (size_t)r0 * CC + cc0) =
                make_float2(acc[f][j][0], acc[f][j][1]);
            *reinterpret_cast<float2*>(dstb + (size_t)(r0 + 8) * CC + cc0) =
                make_float2(acc[f][j][2], acc[f][j][3]);
        }
    }
}

// ---------------- per-row max + 1/sum(exp) + E=exp(K-m) bf16 hi/lo writeback ----------------
__global__ void __launch_bounds__(256)
rowstats_econv()
{
    const size_t row = blockIdx.x;  // 0..2047 == b*256 + o
    const float4* kr = reinterpret_cast<const float4*>(g_k) + row * (NNS / 4);
    const int t = threadIdx.x;

    float4 v[16];
    float mx = -3.402823466e38f;
#pragma unroll
    for (int i = 0; i < 16; ++i) {
        v[i] = kr[t + (i << 8)];
        mx = fmaxf(mx, fmaxf(fmaxf(v[i].x, v[i].y), fmaxf(v[i].z, v[i].w)));
    }
    __shared__ float red[8];
    __shared__ float bmax;
#pragma unroll
    for (int o = 16; o; o >>= 1) mx = fmaxf(mx, __shfl_xor_sync(0xffffffffu, mx, o));
    if ((t & 31) == 0) red[t >> 5] = mx;
    __syncthreads();
    if (t < 32) {
        float x2 = (t < 8) ? red[t] : -3.402823466e38f;
#pragma unroll
        for (int o = 4; o; o >>= 1) x2 = fmaxf(x2, __shfl_xor_sync(0xffffffffu, x2, o));
        if (t == 0) bmax = x2;
    }
    __syncthreads();
    const float m = bmax;

    uint2* eh = reinterpret_cast<uint2*>(g_e_h + row * NNS);
    uint2* el = reinterpret_cast<uint2*>(g_e_l + row * NNS);
    float s = 0.f;
#pragma unroll
    for (int i = 0; i < 16; ++i) {
        float ex = __expf(v[i].x - m), ey = __expf(v[i].y - m);
        float ez = __expf(v[i].z - m), ew = __expf(v[i].w - m);
        s += ex + ey + ez + ew;
        const int q = t + (i << 8);
        eh[q] = make_uint2(pack2(ex, ey), pack2(ez, ew));
        el[q] = make_uint2(pack2(ex - hi_of(ex), ey - hi_of(ey)),
                           pack2(ez - hi_of(ez), ew - hi_of(ew)));
    }
#pragma unroll
    for (int o = 16; o; o >>= 1) s += __shfl_xor_sync(0xffffffffu, s, o);
    if ((t & 31) == 0) red[t >> 5] = s;
    __syncthreads();
    if (t < 32) {
        float x2 = (t < 8) ? red[t] : 0.f;
#pragma unroll
        for (int o = 4; o; o >>= 1) x2 += __shfl_xor_sync(0xffffffffu, x2, o);
        if (t == 0) { g_m[row] = m; g_s[row] = 1.0f / x2; }
    }
}

// ---------------- reduce the 16 split partials into g_Sp ----------------
__global__ void __launch_bounds__(256)
reduce_sp()
{
    const int idx = blockIdx.x * 256 + threadIdx.x;
    const float4* src = reinterpret_cast<const float4*>(g_Spp);
    float4 a = make_float4(0.f, 0.f, 0.f, 0.f);
#pragma unroll
    for (int s = 0; s < SPLITS; ++s) {
        float4 v = src[(long)s * (BB * CC * CC / 4) + idx];
        a.x += v.x; a.y += v.y; a.z += v.z; a.w += v.w;
    }
    reinterpret_cast<float4*>(g_Sp)[idx] = a;
}

// ---------------- small 256^3 GEMMs (R8 VERBATIM, fp32 P2 output) ----------------
template <int MODE>
__global__ void __launch_bounds__(256)
sgemm_small(const float* __restrict__ in0, const float* __restrict__ in1,
            const float* __restrict__ gamma, const float* __restrict__ rvar)
{
    const int LD = CC;
    const int b = blockIdx.z;
    const float* A = (MODE == 0) ? in0 : (MODE == 1) ? (g_Sp + (long)b * CC * CC) : g_A0;
    const float* Bm = (MODE == 0) ? in1 : (MODE == 1) ? in0 : (g_U + (long)b * CC * CC);
    float* Cm = (MODE == 0) ? g_A0 : (MODE == 1) ? (g_U + (long)b * CC * CC)
                                                  : (g_P2 + (long)b * CC * CC);
    const float* ks = (MODE == 1) ? (g_s + (long)b * CC) : nullptr;
    const int m0 = blockIdx.y * 64, n0 = blockIdx.x * 64;

    __shared__ float As[16][65];
    __shared__ float Bs[16][65];

    const int tid = threadIdx.x;
    const int tx = tid & 15, ty = tid >> 4;
    float acc[4][4] = {};

    for (int k0 = 0; k0 < CC; k0 += 16) {
#pragma unroll
        for (int p = 0; p < 4; ++p) {
            int idx = tid + p * 256;
            if (MODE == 1) {
                int kk = idx >> 6, mm = idx & 63;
                As[kk][mm] = A[(long)(k0 + kk) * LD + m0 + mm] * ks[k0 + kk];
            } else {
                int mm = idx >> 4, kk = idx & 15;
                As[kk][mm] = A[(long)(m0 + mm) * LD + k0 + kk];
            }
            int kk2 = idx >> 6, nn2 = idx & 63;
            Bs[kk2][nn2] = Bm[(long)(k0 + kk2) * LD + n0 + nn2];
        }
        __syncthreads();
#pragma unroll
        for (int kk = 0; kk < 16; ++kk) {
            float a[4], bb[4];
#pragma unroll
            for (int i = 0; i < 4; ++i) { a[i] = As[kk][ty * 4 + i]; bb[i] = Bs[kk][tx * 4 + i]; }
#pragma unroll
            for (int i = 0; i < 4; ++i)
#pragma unroll
                for (int j = 0; j < 4; ++j) acc[i][j] += a[i] * bb[j];
        }
        __syncthreads();
    }

#pragma unroll
    for (int i = 0; i < 4; ++i) {
        int mg = m0 + ty * 4 + i;
        float sc = (MODE == 2) ? gamma[mg] * rsqrtf(rvar[mg] + BN_EPS) : 1.f;
#pragma unroll
        for (int j = 0; j < 4; ++j)
            Cm[(long)mg * LD + n0 + tx * 4 + j] = acc[i][j] * sc;
    }
}

// ---------------- launch ----------------
extern "C" void kernel_launch(void* const* d_in, const int* in_sizes, int n_in,
                              void* d_out, int out_size)
{
    const float* x      = (const float*)d_in[0];
    const float* w_qkv  = (const float*)d_in[1];
    const float* w_proj = (const float*)d_in[2];
    const float* gamma  = (const float*)d_in[3];
    const float* beta   = (const float*)d_in[4];
    const float* rmean  = (const float*)d_in[5];
    const float* rvar   = (const float*)d_in[6];
    float* out = (float*)d_out;

    cudaFuncSetAttribute((const void*)mma_big<0>, cudaFuncAttributeMaxDynamicSharedMemorySize, SMEM_MMA);
    cudaFuncSetAttribute((const void*)mma_big<1>, cudaFuncAttributeMaxDynamicSharedMemorySize, SMEM_MMA);
    cudaFuncSetAttribute((const void*)mma_ctx,    cudaFuncAttributeMaxDynamicSharedMemorySize, SMEM_MMA);

    // 0) X -> xt (transposed) and xn (straight) bf16 hi/lo
    transpose_split<<<dim3(NNS / 32, CC / 32, BB), dim3(32, 8)>>>(x);

    // 1) g_k = Wk @ X   (Wk = w_qkv rows [256,512))
    mma_big<0><<<dim3(NNS / 128, 2, BB), 256, SMEM_MMA>>>(w_qkv + CC * CC, nullptr,
                                                          nullptr, nullptr, nullptr, nullptr);

    // 2) softmax stats + E = exp(K-m) bf16 hi/lo
    rowstats_econv<<<BB * CC, 256>>>();

    // 3) split-K partials: E @ X^T -> g_Spp
    mma_ctx<<<dim3(4, SPLITS, BB), 256, SMEM_MMA>>>();

    // 3b) reduce partials -> g_Sp
    reduce_sp<<<512, 256>>>();

    // 4) g_A0 = Wproj @ Wv
    sgemm_small<0><<<dim3(4, 4, 1), 256>>>(w_proj, w_qkv + 2 * CC * CC, nullptr, nullptr);

    // 5) g_U[b] = diag(1/s)-weighted S'^T @ Wq
    sgemm_small<1><<<dim3(4, 4, BB), 256>>>(w_qkv, nullptr, nullptr, nullptr);

    // 6) g_P2[b] (fp32) = diag(inv) * (A0 @ U[b])
    sgemm_small<2><<<dim3(4, 4, BB), 256>>>(nullptr, nullptr, gamma, rvar);

    // 7) out = relu(P2 @ X + (beta - mean*inv))
    mma_big<1><<<dim3(NNS / 128, 2, BB), 256, SMEM_MMA>>>(nullptr, out,
                                                          gamma, beta, rmean, rvar);
}

// round 17
// speedup vs baseline: 2.0836x; 1.4201x over previous
#include <cuda_runtime.h>
#include <cuda_bf16.h>
#include <cuda_fp16.h>
#include <cstdint>

#define BB 8
#define CC 256
#define NNS 16384
#define BN_EPS 1e-5f
#define SPLITS 16

// ---------------- scratch (static device globals; no allocation allowed) ----------------
__device__ __align__(16) float g_k[(size_t)BB * CC * NNS];              // fp32 K = Wk @ X
__device__ __align__(16) float g_m[BB * CC];                            // per-row max
__device__ __align__(16) float g_s[BB * CC];                            // per-row 1/sum(exp)
__device__ __align__(16) float g_Spp[(size_t)SPLITS * BB * CC * CC];    // split-K partials
__device__ __align__(16) float g_Sp[BB * CC * CC];                      // S' reduced
__device__ __align__(16) float g_A0[CC * CC];                           // Wproj @ Wv
__device__ __align__(16) float g_U[BB * CC * CC];                       // weighted S'^T @ Wq
__device__ __align__(16) float g_P2[BB * CC * CC];                      // diag(inv) * A0 @ U (fp32)
__device__ __align__(16) __nv_bfloat16 g_xt_h[(size_t)BB * NNS * CC];   // X^T hi [b][n][c] (bf16, K-GEMM)
__device__ __align__(16) __nv_bfloat16 g_xt_l[(size_t)BB * NNS * CC];   // X^T lo
__device__ __align__(16) __half g_xt_f[(size_t)BB * NNS * CC];          // X^T fp16 [b][n][c] (final GEMM)
__device__ __align__(16) __half g_xn_f[(size_t)BB * CC * NNS];          // X   fp16 [b][c][n] (ctx B)
__device__ __align__(16) __half g_e_f[(size_t)BB * CC * NNS];           // exp(K-m) fp16 [b][o][n] (ctx A)

// ================= helpers (base-sm_103-safe PTX only) =================
__device__ __forceinline__ uint32_t smem_to_u32(const void* p) {
    uint32_t a;
    asm("{ .reg .u64 t; cvta.to.shared.u64 t, %1; cvt.u32.u64 %0, t; }" : "=r"(a) : "l"(p));
    return a;
}
__device__ __forceinline__ void ldsm4(uint32_t* r, uint32_t addr) {
    asm volatile("ldmatrix.sync.aligned.m8n8.x4.shared.b16 {%0,%1,%2,%3}, [%4];"
                 : "=r"(r[0]), "=r"(r[1]), "=r"(r[2]), "=r"(r[3]) : "r"(addr));
}
__device__ __forceinline__ void mma_bf16(float* c, const uint32_t* a, const uint32_t* b) {
    asm volatile("mma.sync.aligned.m16n8k16.row.col.f32.bf16.bf16.f32 "
                 "{%0,%1,%2,%3}, {%4,%5,%6,%7}, {%8,%9}, {%0,%1,%2,%3};"
                 : "+f"(c[0]), "+f"(c[1]), "+f"(c[2]), "+f"(c[3])
                 : "r"(a[0]), "r"(a[1]), "r"(a[2]), "r"(a[3]), "r"(b[0]), "r"(b[1]));
}
__device__ __forceinline__ void mma_f16(float* c, const uint32_t* a, const uint32_t* b) {
    asm volatile("mma.sync.aligned.m16n8k16.row.col.f32.f16.f16.f32 "
                 "{%0,%1,%2,%3}, {%4,%5,%6,%7}, {%8,%9}, {%0,%1,%2,%3};"
                 : "+f"(c[0]), "+f"(c[1]), "+f"(c[2]), "+f"(c[3])
                 : "r"(a[0]), "r"(a[1]), "r"(a[2]), "r"(a[3]), "r"(b[0]), "r"(b[1]));
}
__device__ __forceinline__ void cp_async16(uint32_t dst, const void* src) {
    asm volatile("cp.async.cg.shared.global [%0], [%1], 16;" :: "r"(dst), "l"(src));
}
#define CP_COMMIT() asm volatile("cp.async.commit_group;" ::: "memory")
#define CP_WAIT0()  asm volatile("cp.async.wait_group 0;" ::: "memory")

__device__ __forceinline__ uint32_t pack2(float a, float b) {
    union { __nv_bfloat162 v; uint32_t u; } cv;
    cv.v = __floats2bfloat162_rn(a, b);
    return cv.u;
}
__device__ __forceinline__ uint32_t pack2h(float a, float b) {
    union { __half2 v; uint32_t u; } cv;
    cv.v = __floats2half2_rn(a, b);
    return cv.u;
}
__device__ __forceinline__ float hi_of(float a) {
    return __bfloat162float(__float2bfloat16(a));
}

// ---------------- SMEM layouts: padded rows of 40 b16 (80 B) -> conflict-free ldmatrix ----------------
#define RSB 80
// bf16 3-term K-GEMM (R12 layout): AH/AL/BH/BL
#define OFF_AH 0
#define OFF_AL 10240
#define OFF_BH 20480
#define OFF_BL 30720
#define STAGE  40960
#define SMEM_MMA (2 * STAGE)            // 81920
// fp16 single-term kernels: A/B only
#define FOFF_A 0
#define FOFF_B 10240
#define FSTAGE 20480
#define SMEM_F16 (2 * FSTAGE)           // 40960

// ---------------- X transpose + splits: bf16 hi/lo [n][c] + fp16 [n][c] + fp16 [c][n] ----------------
__global__ void __launch_bounds__(256)
transpose_split(const float* __restrict__ x)
{
    __shared__ float sm[32][33];
    const int b = blockIdx.z, c0 = blockIdx.y * 32, n0 = blockIdx.x * 32;
    const int tx = threadIdx.x, ty = threadIdx.y;   // 32 x 8
    const float* xs = x + ((size_t)b * CC + c0) * NNS + n0;
    float v[4];
#pragma unroll
    for (int i = 0; i < 4; ++i) {
        v[i] = xs[(size_t)(ty + i * 8) * NNS + tx];
        sm[ty + i * 8][tx] = v[i];
    }
    // straight layout [c][n] fp16 (ctx B operand)
    const size_t nbase = ((size_t)b * CC + c0) * NNS + n0;
#pragma unroll
    for (int i = 0; i < 4; ++i) {
        int c = ty + i * 8;
        g_xn_f[nbase + (size_t)c * NNS + tx] = __float2half(v[i]);
    }
    __syncthreads();
    // transposed layout [n][c]: bf16 hi/lo (K-GEMM) + fp16 (final GEMM)
    const size_t obase = ((size_t)b * NNS + n0) * CC + c0;
#pragma unroll
    for (int i = 0; i < 4; ++i) {
        int n = ty + i * 8;
        float f = sm[tx][n];
        __nv_bfloat16 h = __float2bfloat16(f);
        g_xt_h[obase + (size_t)n * CC + tx] = h;
        g_xt_l[obase + (size_t)n * CC + tx] = __float2bfloat16(f - __bfloat162float(h));
        g_xt_f[obase + (size_t)n * CC + tx] = __float2half(f);
    }
}

// ---------------- K-GEMM (R12 VERBATIM, bf16 3-term): g_k[b] = Wk(fp32, reg-pipelined) @ Xt_bf16[b] ----------------
__global__ void __launch_bounds__(256)
mma_bigK(const float* __restrict__ Ap_)
{
    extern __shared__ __align__(16) char smem[];
    const int tid = threadIdx.x, lid = tid & 31, wid = tid >> 5;
    const int wm = wid & 1, wn = wid >> 1;
    const int b = blockIdx.z, m0 = blockIdx.y * 128, n0 = blockIdx.x * 128;
    const float* A = Ap_ + (size_t)m0 * CC;
    const __nv_bfloat16* bhg = g_xt_h + ((size_t)b * NNS + n0) * CC;
    const __nv_bfloat16* blg = g_xt_l + ((size_t)b * NNS + n0) * CC;
    const uint32_t sb = smem_to_u32(smem);

    float acc[4][4][4];
#pragma unroll
    for (int f = 0; f < 4; ++f)
#pragma unroll
        for (int j = 0; j < 4; ++j)
#pragma unroll
            for (int e = 0; e < 4; ++e) acc[f][j][e] = 0.f;

    float4 areg[2];
    auto ldgA = [&](int ks) {
#pragma unroll
        for (int i = 0; i < 2; ++i) {
            int idx = tid + i * 256;
            int r = idx >> 2, q = idx & 3;
            areg[i] = *reinterpret_cast<const float4*>(A + ks * 16 + (size_t)r * CC + q * 4);
        }
    };
    // NOTE: R12 staged A in k32 slices with 4 float4s; keep exactly that.
    float4 areg4[4];
    auto ldgA32 = [&](int ks) {
#pragma unroll
        for (int i = 0; i < 4; ++i) {
            int idx = tid + i * 256;             // 0..1023 float4s
            int r = idx >> 3, q = idx & 7;
            areg4[i] = *reinterpret_cast<const float4*>(A + ks * 32 + (size_t)r * CC + q * 4);
        }
    };
    auto stsA32 = [&](int st) {
        char* bp = smem + st * STAGE;
#pragma unroll
        for (int i = 0; i < 4; ++i) {
            int idx = tid + i * 256;
            int r = idx >> 3, q = idx & 7;
            float4 v = areg4[i];
            uint32_t h01 = pack2(v.x, v.y), h23 = pack2(v.z, v.w);
            uint32_t l01 = pack2(v.x - hi_of(v.x), v.y - hi_of(v.y));
            uint32_t l23 = pack2(v.z - hi_of(v.z), v.w - hi_of(v.w));
            *reinterpret_cast<uint2*>(bp + OFF_AH + r * RSB + q * 8) = make_uint2(h01, h23);
            *reinterpret_cast<uint2*>(bp + OFF_AL + r * RSB + q * 8) = make_uint2(l01, l23);
        }
    };
    (void)ldgA; (void)areg;
    auto loadB = [&](int ks, int st) {
        uint32_t dst = sb + st * STAGE;
#pragma unroll
        for (int i = 0; i < 2; ++i) {
            int idx = tid + i * 256;
            int r = idx >> 2, q = idx & 3;
            cp_async16(dst + OFF_BH + r * RSB + q * 16, bhg + (size_t)r * CC + ks * 32 + q * 8);
            cp_async16(dst + OFF_BL + r * RSB + q * 16, blg + (size_t)r * CC + ks * 32 + q * 8);
        }
    };
    auto compute = [&](int st) {
        const uint32_t s0 = sb + st * STAGE;
#pragma unroll
        for (int k16 = 0; k16 < 2; ++k16) {
            const int ko = k16 * 16;
            uint32_t ah[4][4], al[4][4], bhf[2][4], blf[2][4];
            const uint32_t acol = (uint32_t)(ko + ((lid >> 4) << 3)) << 1;
#pragma unroll
            for (int f = 0; f < 4; ++f) {
                uint32_t row = (uint32_t)(wm * 64 + f * 16 + (lid & 15));
                ldsm4(ah[f], s0 + OFF_AH + row * RSB + acol);
                ldsm4(al[f], s0 + OFF_AL + row * RSB + acol);
            }
            const uint32_t bcol = (uint32_t)(ko + (((lid >> 3) & 1) << 3)) << 1;
#pragma unroll
            for (int p = 0; p < 2; ++p) {
                uint32_t nr = (uint32_t)(wn * 32 + p * 16 + (lid & 7) + ((lid >> 4) << 3));
                ldsm4(bhf[p], s0 + OFF_BH + nr * RSB + bcol);
                ldsm4(blf[p], s0 + OFF_BL + nr * RSB + bcol);
            }
#pragma unroll
            for (int f = 0; f < 4; ++f)
#pragma unroll
                for (int j = 0; j < 4; ++j) {
                    const int p = j >> 1, h = j & 1;
                    uint32_t bh2[2] = {bhf[p][h * 2], bhf[p][h * 2 + 1]};
                    uint32_t bl2[2] = {blf[p][h * 2], blf[p][h * 2 + 1]};
                    mma_bf16(acc[f][j], ah[f], bh2);
                    mma_bf16(acc[f][j], ah[f], bl2);
                    mma_bf16(acc[f][j], al[f], bh2);
                }
        }
    };

    loadB(0, 0); CP_COMMIT();
    ldgA32(0); stsA32(0);
    for (int s = 0; s < 8; ++s) {
        CP_WAIT0();
        __syncthreads();
        if (s < 7) { loadB(s + 1, (s + 1) & 1); CP_COMMIT(); ldgA32(s + 1); }
        compute(s & 1);
        if (s < 7) stsA32((s + 1) & 1);
    }

    float* outb = g_k + (size_t)b * CC * NNS;
    const int colb = n0 + wn * 32 + 2 * (lid & 3);
#pragma unroll
    for (int f = 0; f < 4; ++f) {
        const int r0 = m0 + wm * 64 + f * 16 + (lid >> 2);
#pragma unroll
        for (int j = 0; j < 4; ++j) {
            const int cc0 = colb + j * 8;
            *reinterpret_cast<float2*>(outb + (size_t)r0 * NNS + cc0) =
                make_float2(acc[f][j][0], acc[f][j][1]);
            *reinterpret_cast<float2*>(outb + (size_t)(r0 + 8) * NNS + cc0) =
                make_float2(acc[f][j][2], acc[f][j][3]);
        }
    }
}

// ---------------- ctx GEMM, fp16 single-term: S'_partial = E_f16 @ Xn_f16^T over 1024 n ----------------
__global__ void __launch_bounds__(256)
mma_ctx_f16()
{
    extern __shared__ __align__(16) char smem[];
    const int tid = threadIdx.x, lid = tid & 31, wid = tid >> 5;
    const int wm = wid & 1, wn = wid >> 1;
    const int o0 = (blockIdx.x >> 1) * 128, c0 = (blockIdx.x & 1) * 128;
    const int split = blockIdx.y, b = blockIdx.z;
    const uint32_t sb = smem_to_u32(smem);

    const size_t ko0 = (size_t)split * 1024;
    const __half* eg = g_e_f + ((size_t)b * CC + o0) * NNS + ko0;
    const __half* xg = g_xn_f + ((size_t)b * CC + c0) * NNS + ko0;

    float acc[4][4][4];
#pragma unroll
    for (int f = 0; f < 4; ++f)
#pragma unroll
        for (int j = 0; j < 4; ++j)
#pragma unroll
            for (int e = 0; e < 4; ++e) acc[f][j][e] = 0.f;

    auto loadT = [&](int ks, int st) {   // two streams, pure cp.async (R12-loadB indexing)
        uint32_t dst = sb + st * FSTAGE;
#pragma unroll
        for (int i = 0; i < 2; ++i) {
            int idx = tid + i * 256;             // 0..511 16B chunks
            int r = idx >> 2, q = idx & 3;
            size_t so = (size_t)r * NNS + (size_t)ks * 32 + q * 8;
            cp_async16(dst + FOFF_A + r * RSB + q * 16, eg + so);
            cp_async16(dst + FOFF_B + r * RSB + q * 16, xg + so);
        }
    };
    auto compute = [&](int st) {
        const uint32_t s0 = sb + st * FSTAGE;
#pragma unroll
        for (int k16 = 0; k16 < 2; ++k16) {
            const int ko = k16 * 16;
            uint32_t af[4][4], bf[2][4];
            const uint32_t acol = (uint32_t)(ko + ((lid >> 4) << 3)) << 1;
#pragma unroll
            for (int f = 0; f < 4; ++f) {
                uint32_t row = (uint32_t)(wm * 64 + f * 16 + (lid & 15));
                ldsm4(af[f], s0 + FOFF_A + row * RSB + acol);
            }
            const uint32_t bcol = (uint32_t)(ko + (((lid >> 3) & 1) << 3)) << 1;
#pragma unroll
            for (int p = 0; p < 2; ++p) {
                uint32_t nr = (uint32_t)(wn * 32 + p * 16 + (lid & 7) + ((lid >> 4) << 3));
                ldsm4(bf[p], s0 + FOFF_B + nr * RSB + bcol);
            }
#pragma unroll
            for (int f = 0; f < 4; ++f)
#pragma unroll
                for (int j = 0; j < 4; ++j) {
                    const int p = j >> 1, h = j & 1;
                    uint32_t b2[2] = {bf[p][h * 2], bf[p][h * 2 + 1]};
                    mma_f16(acc[f][j], af[f], b2);
                }
        }
    };

    loadT(0, 0); CP_COMMIT();
    for (int s = 0; s < 32; ++s) {
        CP_WAIT0();
        __syncthreads();
        if (s < 31) { loadT(s + 1, (s + 1) & 1); CP_COMMIT(); }
        compute(s & 1);
    }

    float* dstb = g_Spp + ((size_t)split * BB + b) * CC * CC;
    const int colb = c0 + wn * 32 + 2 * (lid & 3);
#pragma unroll
    for (int f = 0; f < 4; ++f) {
        const int r0 = o0 + wm * 64 + f * 16 + (lid >> 2);
#pragma unroll
        for (int j = 0; j < 4; ++j) {
            const int cc0 = colb + j * 8;
            *reinterpret_cast<float2*>(dstb + (size_t)r0 * CC + cc0) =
                make_float2(acc[f][j][0], acc[f][j][1]);
            *reinterpret_cast<float2*>(dstb + (size_t)(r0 + 8) * CC + cc0) =
                make_float2(acc[f][j][2], acc[f][j][3]);
        }
    }
}

// ---------------- final GEMM, fp16 single-term: out = relu(P2 @ Xt_f16 + bn_bias) ----------------
__global__ void __launch_bounds__(256)
mma_big_f16(float* __restrict__ outp,
            const float* __restrict__ gamma, const float* __restrict__ beta,
            const float* __restrict__ rmean, const float* __restrict__ rvar)
{
    extern __shared__ __align__(16) char smem[];
    const int tid = threadIdx.x, lid = tid & 31, wid = tid >> 5;
    const int wm = wid & 1, wn = wid >> 1;
    const int b = blockIdx.z, m0 = blockIdx.y * 128, n0 = blockIdx.x * 128;
    const float* A = g_P2 + (size_t)b * CC * CC + (size_t)m0 * CC;
    const __half* bfg = g_xt_f + ((size_t)b * NNS + n0) * CC;
    const uint32_t sb = smem_to_u32(smem);

    float acc[4][4][4];
#pragma unroll
    for (int f = 0; f < 4; ++f)
#pragma unroll
        for (int j = 0; j < 4; ++j)
#pragma unroll
            for (int e = 0; e < 4; ++e) acc[f][j][e] = 0.f;

    float4 areg[4];                      // next A k32 slice (128x32 fp32), reg-staged
    auto ldgA = [&](int ks) {
#pragma unroll
        for (int i = 0; i < 4; ++i) {
            int idx = tid + i * 256;
            int r = idx >> 3, q = idx & 7;
            areg[i] = *reinterpret_cast<const float4*>(A + ks * 32 + (size_t)r * CC + q * 4);
        }
    };
    auto stsA = [&](int st) {            // fp32 -> fp16 single array
        char* bp = smem + st * FSTAGE;
#pragma unroll
        for (int i = 0; i < 4; ++i) {
            int idx = tid + i * 256;
            int r = idx >> 3, q = idx & 7;
            float4 v = areg[i];
            *reinterpret_cast<uint2*>(bp + FOFF_A + r * RSB + q * 8) =
                make_uint2(pack2h(v.x, v.y), pack2h(v.z, v.w));
        }
    };
    auto loadB = [&](int ks, int st) {
        uint32_t dst = sb + st * FSTAGE;
#pragma unroll
        for (int i = 0; i < 2; ++i) {
            int idx = tid + i * 256;
            int r = idx >> 2, q = idx & 3;
            cp_async16(dst + FOFF_B + r * RSB + q * 16, bfg + (size_t)r * CC + ks * 32 + q * 8);
        }
    };
    auto compute = [&](int st) {
        const uint32_t s0 = sb + st * FSTAGE;
#pragma unroll
        for (int k16 = 0; k16 < 2; ++k16) {
            const int ko = k16 * 16;
            uint32_t af[4][4], bf[2][4];
            const uint32_t acol = (uint32_t)(ko + ((lid >> 4) << 3)) << 1;
#pragma unroll
            for (int f = 0; f < 4; ++f) {
                uint32_t row = (uint32_t)(wm * 64 + f * 16 + (lid & 15));
                ldsm4(af[f], s0 + FOFF_A + row * RSB + acol);
            }
            const uint32_t bcol = (uint32_t)(ko + (((lid >> 3) & 1) << 3)) << 1;
#pragma unroll
            for (int p = 0; p < 2; ++p) {
                uint32_t nr = (uint32_t)(wn * 32 + p * 16 + (lid & 7) + ((lid >> 4) << 3));
                ldsm4(bf[p], s0 + FOFF_B + nr * RSB + bcol);
            }
#pragma unroll
            for (int f = 0; f < 4; ++f)
#pragma unroll
                for (int j = 0; j < 4; ++j) {
                    const int p = j >> 1, h = j & 1;
                    uint32_t b2[2] = {bf[p][h * 2], bf[p][h * 2 + 1]};
                    mma_f16(acc[f][j], af[f], b2);
                }
        }
    };

    loadB(0, 0); CP_COMMIT();
    ldgA(0); stsA(0);
    for (int s = 0; s < 8; ++s) {
        CP_WAIT0();
        __syncthreads();
        if (s < 7) { loadB(s + 1, (s + 1) & 1); CP_COMMIT(); ldgA(s + 1); }
        compute(s & 1);
        if (s < 7) stsA((s + 1) & 1);
    }

    const int colb = n0 + wn * 32 + 2 * (lid & 3);
    float* outb = outp + (size_t)b * CC * NNS;
#pragma unroll
    for (int f = 0; f < 4; ++f) {
        const int r0 = m0 + wm * 64 + f * 16 + (lid >> 2);
        float i0 = gamma[r0] * rsqrtf(rvar[r0] + BN_EPS);
        float i1 = gamma[r0 + 8] * rsqrtf(rvar[r0 + 8] + BN_EPS);
        float bias0 = beta[r0] - rmean[r0] * i0;
        float bias1 = beta[r0 + 8] - rmean[r0 + 8] * i1;
#pragma unroll
        for (int j = 0; j < 4; ++j) {
            const int cc0 = colb + j * 8;
            float2 v0 = make_float2(fmaxf(acc[f][j][0] + bias0, 0.f),
                                    fmaxf(acc[f][j][1] + bias0, 0.f));
            float2 v1 = make_float2(fmaxf(acc[f][j][2] + bias1, 0.f),
                                    fmaxf(acc[f][j][3] + bias1, 0.f));
            *reinterpret_cast<float2*>(outb + (size_t)r0 * NNS + cc0)       = v0;
            *reinterpret_cast<float2*>(outb + (size_t)(r0 + 8) * NNS + cc0) = v1;
        }
    }
}

// ---------------- per-row max + 1/sum(exp) + E=exp(K-m) fp16 writeback ----------------
__global__ void __launch_bounds__(256)
rowstats_econv()
{
    const size_t row = blockIdx.x;  // 0..2047 == b*256 + o
    const float4* kr = reinterpret_cast<const float4*>(g_k) + row * (NNS / 4);
    const int t = threadIdx.x;

    float4 v[16];
    float mx = -3.402823466e38f;
#pragma unroll
    for (int i = 0; i < 16; ++i) {
        v[i] = kr[t + (i << 8)];
        mx = fmaxf(mx, fmaxf(fmaxf(v[i].x, v[i].y), fmaxf(v[i].z, v[i].w)));
    }
    __shared__ float red[8];
    __shared__ float bmax;
#pragma unroll
    for (int o = 16; o; o >>= 1) mx = fmaxf(mx, __shfl_xor_sync(0xffffffffu, mx, o));
    if ((t & 31) == 0) red[t >> 5] = mx;
    __syncthreads();
    if (t < 32) {
        float x2 = (t < 8) ? red[t] : -3.402823466e38f;
#pragma unroll
        for (int o = 4; o; o >>= 1) x2 = fmaxf(x2, __shfl_xor_sync(0xffffffffu, x2, o));
        if (t == 0) bmax = x2;
    }
    __syncthreads();
    const float m = bmax;

    uint2* ef = reinterpret_cast<uint2*>(g_e_f + row * NNS);
    float s = 0.f;
#pragma unroll
    for (int i = 0; i < 16; ++i) {
        float ex = __expf(v[i].x - m), ey = __expf(v[i].y - m);
        float ez = __expf(v[i].z - m), ew = __expf(v[i].w - m);
        s += ex + ey + ez + ew;
        const int q = t + (i << 8);                 // float4 index within row
        ef[q] = make_uint2(pack2h(ex, ey), pack2h(ez, ew));
    }
#pragma unroll
    for (int o = 16; o; o >>= 1) s += __shfl_xor_sync(0xffffffffu, s, o);
    if ((t & 31) == 0) red[t >> 5] = s;
    __syncthreads();
    if (t < 32) {
        float x2 = (t < 8) ? red[t] : 0.f;
#pragma unroll
        for (int o = 4; o; o >>= 1) x2 += __shfl_xor_sync(0xffffffffu, x2, o);
        if (t == 0) { g_m[row] = m; g_s[row] = 1.0f / x2; }
    }
}

// ---------------- reduce the 16 split partials into g_Sp ----------------
__global__ void __launch_bounds__(256)
reduce_sp()
{
    const int idx = blockIdx.x * 256 + threadIdx.x;
    const float4* src = reinterpret_cast<const float4*>(g_Spp);
    float4 a = make_float4(0.f, 0.f, 0.f, 0.f);
#pragma unroll
    for (int s = 0; s < SPLITS; ++s) {
        float4 v = src[(long)s * (BB * CC * CC / 4) + idx];
        a.x += v.x; a.y += v.y; a.z += v.z; a.w += v.w;
    }
    reinterpret_cast<float4*>(g_Sp)[idx] = a;
}

// ---------------- small 256^3 GEMMs (R8 VERBATIM, fp32 P2 output) ----------------
template <int MODE>
__global__ void __launch_bounds__(256)
sgemm_small(const float* __restrict__ in0, const float* __restrict__ in1,
            const float* __restrict__ gamma, const float* __restrict__ rvar)
{
    const int LD = CC;
    const int b = blockIdx.z;
    const float* A = (MODE == 0) ? in0 : (MODE == 1) ? (g_Sp + (long)b * CC * CC) : g_A0;
    const float* Bm = (MODE == 0) ? in1 : (MODE == 1) ? in0 : (g_U + (long)b * CC * CC);
    float* Cm = (MODE == 0) ? g_A0 : (MODE == 1) ? (g_U + (long)b * CC * CC)
                                                  : (g_P2 + (long)b * CC * CC);
    const float* ks = (MODE == 1) ? (g_s + (long)b * CC) : nullptr;
    const int m0 = blockIdx.y * 64, n0 = blockIdx.x * 64;

    __shared__ float As[16][65];
    __shared__ float Bs[16][65];

    const int tid = threadIdx.x;
    const int tx = tid & 15, ty = tid >> 4;
    float acc[4][4] = {};

    for (int k0 = 0; k0 < CC; k0 += 16) {
#pragma unroll
        for (int p = 0; p < 4; ++p) {
            int idx = tid + p * 256;
            if (MODE == 1) {
                int kk = idx >> 6, mm = idx & 63;
                As[kk][mm] = A[(long)(k0 + kk) * LD + m0 + mm] * ks[k0 + kk];
            } else {
                int mm = idx >> 4, kk = idx & 15;
                As[kk][mm] = A[(long)(m0 + mm) * LD + k0 + kk];
            }
            int kk2 = idx >> 6, nn2 = idx & 63;
            Bs[kk2][nn2] = Bm[(long)(k0 + kk2) * LD + n0 + nn2];
        }
        __syncthreads();
#pragma unroll
        for (int kk = 0; kk < 16; ++kk) {
            float a[4], bb[4];
#pragma unroll
            for (int i = 0; i < 4; ++i) { a[i] = As[kk][ty * 4 + i]; bb[i] = Bs[kk][tx * 4 + i]; }
#pragma unroll
            for (int i = 0; i < 4; ++i)
#pragma unroll
                for (int j = 0; j < 4; ++j) acc[i][j] += a[i] * bb[j];
        }
        __syncthreads();
    }

#pragma unroll
    for (int i = 0; i < 4; ++i) {
        int mg = m0 + ty * 4 + i;
        float sc = (MODE == 2) ? gamma[mg] * rsqrtf(rvar[mg] + BN_EPS) : 1.f;
#pragma unroll
        for (int j = 0; j < 4; ++j)
            Cm[(long)mg * LD + n0 + tx * 4 + j] = acc[i][j] * sc;
    }
}

// ---------------- launch ----------------
extern "C" void kernel_launch(void* const* d_in, const int* in_sizes, int n_in,
                              void* d_out, int out_size)
{
    const float* x      = (const float*)d_in[0];
    const float* w_qkv  = (const float*)d_in[1];
    const float* w_proj = (const float*)d_in[2];
    const float* gamma  = (const float*)d_in[3];
    const float* beta   = (const float*)d_in[4];
    const float* rmean  = (const float*)d_in[5];
    const float* rvar   = (const float*)d_in[6];
    float* out = (float*)d_out;

    cudaFuncSetAttribute((const void*)mma_bigK, cudaFuncAttributeMaxDynamicSharedMemorySize, SMEM_MMA);

    // 0) X -> xt bf16 hi/lo + xt fp16 + xn fp16
    transpose_split<<<dim3(NNS / 32, CC / 32, BB), dim3(32, 8)>>>(x);

    // 1) g_k = Wk @ X   (bf16 3-term — feeds exp, needs precision)
    mma_bigK<<<dim3(NNS / 128, 2, BB), 256, SMEM_MMA>>>(w_qkv + CC * CC);

    // 2) softmax stats + E = exp(K-m) fp16
    rowstats_econv<<<BB * CC, 256>>>();

    // 3) split-K partials: E @ X^T -> g_Spp   (fp16 single-term)
    mma_ctx_f16<<<dim3(4, SPLITS, BB), 256, SMEM_F16>>>();

    // 3b) reduce partials -> g_Sp
    reduce_sp<<<512, 256>>>();

    // 4) g_A0 = Wproj @ Wv
    sgemm_small<0><<<dim3(4, 4, 1), 256>>>(w_proj, w_qkv + 2 * CC * CC, nullptr, nullptr);

    // 5) g_U[b] = diag(1/s)-weighted S'^T @ Wq
    sgemm_small<1><<<dim3(4, 4, BB), 256>>>(w_qkv, nullptr, nullptr, nullptr);

    // 6) g_P2[b] (fp32) = diag(inv) * (A0 @ U[b])
    sgemm_small<2><<<dim3(4, 4, BB), 256>>>(nullptr, nullptr, gamma, rvar);

    // 7) out = relu(P2 @ X + (beta - mean*inv))   (fp16 single-term)
    mma_big_f16<<<dim3(NNS / 128, 2, BB), 256, SMEM_F16>>>(out, gamma, beta, rmean, rvar);
}